// round 3
// baseline (speedup 1.0000x reference)
#include <cuda_runtime.h>
#include <math.h>

typedef unsigned long long ull;

#define Bz 32
#define Sz 512
#define Ez 256
#define Uz 1024
#define U2 2048
#define BSz (Bz*Sz)   // 16384

#define NBLK 128
#define NTHR 256

// -------- scratch (device globals; no allocation allowed) --------
__device__ float g_Xg[(size_t)BSz * U2];
__device__ float g_Xc[(size_t)BSz * Uz];
__device__ float g_y0[(size_t)BSz * Uz];
__device__ float g_h [Bz * Uz];
__device__ float g_u [Bz * Uz];
__device__ float g_a [Bz * Uz];

// grid barrier state
__device__ unsigned int g_count = 0;
__device__ volatile unsigned int g_gen = 0;

// -------- f32x2 packed-math helpers --------
__device__ __forceinline__ void fma2(ull& d, ull a, ull b) {
    asm("fma.rn.f32x2 %0, %1, %2, %0;" : "+l"(d) : "l"(a), "l"(b));
}
__device__ __forceinline__ void add2(ull& d, ull a) {
    asm("add.rn.f32x2 %0, %1, %0;" : "+l"(d) : "l"(a));
}
__device__ __forceinline__ float2 unpack2(ull v) {
    float2 r; asm("mov.b64 {%0,%1}, %2;" : "=f"(r.x), "=f"(r.y) : "l"(v)); return r;
}
__device__ __forceinline__ ull dup1(float x) {
    ull r; asm("mov.b64 %0, {%1,%1};" : "=l"(r) : "f"(x)); return r;
}

__device__ __forceinline__ void gsync() {
    __syncthreads();
    if (threadIdx.x == 0) {
        __threadfence();
        unsigned int gen = g_gen;
        if (atomicAdd(&g_count, 1u) == NBLK - 1u) {
            g_count = 0;
            __threadfence();
            g_gen = gen + 1u;
        } else {
            while (g_gen == gen) { }
        }
        __threadfence();
    }
    __syncthreads();
}

// ------------------------------------------------------------------
// C[M,N] = A @ W + bias with f32x2 packed FMA.
__global__ __launch_bounds__(256) void sgemm_bias(
    const float* __restrict__ Abase, const int* __restrict__ xidx,
    const float* __restrict__ W, const float* __restrict__ bias,
    float* __restrict__ C, int M, int N, int K)
{
    __shared__ ull   As2[8][132];   // dup A values: As2[k][row] = (a,a)
    __shared__ float Bs[8][128];

    int tid = threadIdx.x;
    int ty = tid >> 4;
    int tx = tid & 15;
    int rowBase = blockIdx.y * 128;
    int colBase = blockIdx.x * 128;

    int arow  = tid >> 1;
    int acol4 = (tid & 1) * 4;
    int am = rowBase + arow;
    const float* arowptr;
    if (xidx) arowptr = Abase + (size_t)xidx[am] * K;
    else      arowptr = Abase + (size_t)am * K;

    int brow  = tid >> 5;
    int bcol4 = (tid & 31) * 4;

    ull acc2[8][4];
#pragma unroll
    for (int i = 0; i < 8; i++)
#pragma unroll
        for (int j = 0; j < 4; j++) acc2[i][j] = 0ULL;

    for (int k0 = 0; k0 < K; k0 += 8) {
        float4 av = *(const float4*)&arowptr[k0 + acol4];
        As2[acol4 + 0][arow] = dup1(av.x);
        As2[acol4 + 1][arow] = dup1(av.y);
        As2[acol4 + 2][arow] = dup1(av.z);
        As2[acol4 + 3][arow] = dup1(av.w);

        *(float4*)&Bs[brow][bcol4] = *(const float4*)&W[(size_t)(k0 + brow) * N + colBase + bcol4];

        __syncthreads();
#pragma unroll
        for (int kk = 0; kk < 8; kk++) {
            ulonglong2 a01 = *(const ulonglong2*)&As2[kk][ty * 8];
            ulonglong2 a23 = *(const ulonglong2*)&As2[kk][ty * 8 + 2];
            ulonglong2 a45 = *(const ulonglong2*)&As2[kk][ty * 8 + 4];
            ulonglong2 a67 = *(const ulonglong2*)&As2[kk][ty * 8 + 6];
            ulonglong2 b01 = *(const ulonglong2*)&Bs[kk][tx * 8];
            ulonglong2 b23 = *(const ulonglong2*)&Bs[kk][tx * 8 + 4];
            ull ar[8] = {a01.x, a01.y, a23.x, a23.y, a45.x, a45.y, a67.x, a67.y};
#pragma unroll
            for (int i = 0; i < 8; i++) {
                fma2(acc2[i][0], ar[i], b01.x);
                fma2(acc2[i][1], ar[i], b01.y);
                fma2(acc2[i][2], ar[i], b23.x);
                fma2(acc2[i][3], ar[i], b23.y);
            }
        }
        __syncthreads();
    }

    int col0 = colBase + tx * 8;
    float4 bia0 = *(const float4*)&bias[col0];
    float4 bia1 = *(const float4*)&bias[col0 + 4];
#pragma unroll
    for (int i = 0; i < 8; i++) {
        int row = rowBase + ty * 8 + i;
        float2 f0 = unpack2(acc2[i][0]);
        float2 f1 = unpack2(acc2[i][1]);
        float2 f2 = unpack2(acc2[i][2]);
        float2 f3 = unpack2(acc2[i][3]);
        float4 v0 = make_float4(f0.x + bia0.x, f0.y + bia0.y, f1.x + bia0.z, f1.y + bia0.w);
        float4 v1 = make_float4(f2.x + bia1.x, f2.y + bia1.y, f3.x + bia1.z, f3.y + bia1.w);
        *(float4*)&C[(size_t)row * N + col0]     = v0;
        *(float4*)&C[(size_t)row * N + col0 + 4] = v1;
    }
}

// ------------------------------------------------------------------
// Persistent GRU scan. 128 blocks x 256 threads, weights SMEM-resident.
// Thread decomposition: kh = tid>>7 (k-half), r = tid&127, b = r>>2, q = r&3.
// Phase1: thread computes 4 gate cols (jg0+q*4..+3) over its 512-k half.
// Phase2: thread computes 2 cand cols (jc0+q*2..+1) over its 512-k half.
// h / a staged into SMEM as duplicated (v,v) u64 for direct FFMA2 operands.
#define SWG_F   16384                        // [1024][16] floats
#define SWC_F   8192                         // [1024][8]  floats
#define SH_PITCH 132                         // u64 pitch per batch row
#define SH_U64  (32 * SH_PITCH)              // one 128-k dup tile: 4224 u64
#define SMEM_BYTES (SWG_F*4 + SWC_F*4 + 2*SH_U64*8)   // 165888

__global__ __launch_bounds__(NTHR) void gru_scan(
    const float* __restrict__ Wgh,   // [1024][2048]
    const float* __restrict__ Wch,   // [1024][1024]
    const float* __restrict__ Xg,    // [16384][2048]
    const float* __restrict__ Xc,    // [16384][1024]
    const float* __restrict__ h0,
    float* __restrict__ y,
    float* __restrict__ s_out)
{
    extern __shared__ char smraw[];
    float* swg = (float*)smraw;              // gate W slice
    float* swc = swg + SWG_F;                // cand W slice
    ull*   shA = (ull*)(swc + SWC_F);        // dup tile for k-half 0
    ull*   shB = shA + SH_U64;               // dup tile for k-half 1
    ull*   sred = shA;                       // reduction scratch (reused)

    const int tid = threadIdx.x;
    const int blk = blockIdx.x;
    const int kh  = tid >> 7;
    const int r   = tid & 127;
    const int b   = r >> 2;
    const int q   = r & 3;
    const int jg0 = blk * 16;
    const int jc0 = blk * 8;

    // ---- preload W slices (once per layer) ----
    for (int i = tid; i < 4096; i += NTHR) {
        int k = i >> 2, c4 = (i & 3) * 4;
        *(float4*)&swg[k * 16 + c4] = *(const float4*)&Wgh[(size_t)k * U2 + jg0 + c4];
    }
    for (int i = tid; i < 2048; i += NTHR) {
        int k = i >> 1, c4 = (i & 1) * 4;
        *(float4*)&swc[k * 8 + c4] = *(const float4*)&Wch[(size_t)k * Uz + jc0 + c4];
    }
    {
        int i = blk * NTHR + tid;
        __stcg(&g_h[i], h0[i]);
    }
    gsync();

    const ull* hb = (kh ? shB : shA) + b * SH_PITCH;

    int srow[4], sc4[4];
#pragma unroll
    for (int rr = 0; rr < 4; rr++) { int idx = tid + rr * NTHR; srow[rr] = idx >> 5; sc4[rr] = (idx & 31) * 4; }

    for (int t = 0; t < Sz; t++) {
        // ================= phase 1: gates =================
        ull acc0 = 0ULL, acc1 = 0ULL;
        {
            float4 pA[4], pB[4];
#pragma unroll
            for (int rr = 0; rr < 4; rr++) {
                pA[rr] = __ldcg((const float4*)&g_h[srow[rr] * Uz + sc4[rr]]);
                pB[rr] = __ldcg((const float4*)&g_h[srow[rr] * Uz + 512 + sc4[rr]]);
            }
            for (int i = 0; i < 4; i++) {
                __syncthreads();
#pragma unroll
                for (int rr = 0; rr < 4; rr++) {
                    int fbase = (srow[rr] * SH_PITCH + sc4[rr]) >> 1;
                    float4 v = pA[rr];
                    ((float4*)shA)[fbase]     = make_float4(v.x, v.x, v.y, v.y);
                    ((float4*)shA)[fbase + 1] = make_float4(v.z, v.z, v.w, v.w);
                    v = pB[rr];
                    ((float4*)shB)[fbase]     = make_float4(v.x, v.x, v.y, v.y);
                    ((float4*)shB)[fbase + 1] = make_float4(v.z, v.z, v.w, v.w);
                }
                __syncthreads();
                if (i < 3) {
                    int kn = (i + 1) * 128;
#pragma unroll
                    for (int rr = 0; rr < 4; rr++) {
                        pA[rr] = __ldcg((const float4*)&g_h[srow[rr] * Uz + kn + sc4[rr]]);
                        pB[rr] = __ldcg((const float4*)&g_h[srow[rr] * Uz + 512 + kn + sc4[rr]]);
                    }
                }
                int k0 = kh ? (512 + i * 128) : (i * 128);
                const char* wp = (const char*)(swg + k0 * 16 + q * 4);
#pragma unroll 16
                for (int kk = 0; kk < 128; kk++) {
                    ull h2 = hb[kk];
                    ulonglong2 w = *(const ulonglong2*)(wp + kk * 64);
                    fma2(acc0, h2, w.x);
                    fma2(acc1, h2, w.y);
                }
            }
        }
        __syncthreads();
        if (kh) { sred[r * 2] = acc0; sred[r * 2 + 1] = acc1; }
        __syncthreads();
        if (!kh) {
            add2(acc0, sred[r * 2]);
            add2(acc1, sred[r * 2 + 1]);
            int jg = jg0 + q * 4;
            int m  = b * Sz + t;
            float4 xg = *(const float4*)&Xg[(size_t)m * U2 + jg];
            float2 a0 = unpack2(acc0), a1 = unpack2(acc1);
            float v0 = 1.f / (1.f + expf(-(xg.x + a0.x)));
            float v1 = 1.f / (1.f + expf(-(xg.y + a0.y)));
            float v2 = 1.f / (1.f + expf(-(xg.z + a1.x)));
            float v3 = 1.f / (1.f + expf(-(xg.w + a1.y)));
            if (jg < Uz) {
                float4 hv = __ldcg((const float4*)&g_h[b * Uz + jg]);
                __stcg((float4*)&g_a[b * Uz + jg],
                       make_float4(v0 * hv.x, v1 * hv.y, v2 * hv.z, v3 * hv.w));
            } else {
                __stcg((float4*)&g_u[b * Uz + jg - Uz], make_float4(v0, v1, v2, v3));
            }
        }
        gsync();

        // ================= phase 2: candidate + update =================
        ull accc = 0ULL;
        {
            float4 pA[4], pB[4];
#pragma unroll
            for (int rr = 0; rr < 4; rr++) {
                pA[rr] = __ldcg((const float4*)&g_a[srow[rr] * Uz + sc4[rr]]);
                pB[rr] = __ldcg((const float4*)&g_a[srow[rr] * Uz + 512 + sc4[rr]]);
            }
            for (int i = 0; i < 4; i++) {
                __syncthreads();
#pragma unroll
                for (int rr = 0; rr < 4; rr++) {
                    int fbase = (srow[rr] * SH_PITCH + sc4[rr]) >> 1;
                    float4 v = pA[rr];
                    ((float4*)shA)[fbase]     = make_float4(v.x, v.x, v.y, v.y);
                    ((float4*)shA)[fbase + 1] = make_float4(v.z, v.z, v.w, v.w);
                    v = pB[rr];
                    ((float4*)shB)[fbase]     = make_float4(v.x, v.x, v.y, v.y);
                    ((float4*)shB)[fbase + 1] = make_float4(v.z, v.z, v.w, v.w);
                }
                __syncthreads();
                if (i < 3) {
                    int kn = (i + 1) * 128;
#pragma unroll
                    for (int rr = 0; rr < 4; rr++) {
                        pA[rr] = __ldcg((const float4*)&g_a[srow[rr] * Uz + kn + sc4[rr]]);
                        pB[rr] = __ldcg((const float4*)&g_a[srow[rr] * Uz + 512 + kn + sc4[rr]]);
                    }
                }
                int k0 = kh ? (512 + i * 128) : (i * 128);
                const char* wp = (const char*)(swc + k0 * 8 + q * 2);
#pragma unroll 16
                for (int kk = 0; kk < 128; kk++) {
                    ull a2v = hb[kk];
                    ull w2  = *(const ull*)(wp + kk * 32);
                    fma2(accc, a2v, w2);
                }
            }
        }
        __syncthreads();
        if (kh) sred[r] = accc;
        __syncthreads();
        if (!kh) {
            add2(accc, sred[r]);
            int jc = jc0 + q * 2;
            int m  = b * Sz + t;
            float2 xc = *(const float2*)&Xc[(size_t)m * Uz + jc];
            float2 cf = unpack2(accc);
            float c0 = tanhf(xc.x + cf.x);
            float c1 = tanhf(xc.y + cf.y);
            float2 uu = __ldcg((const float2*)&g_u[b * Uz + jc]);
            float2 ho = __ldcg((const float2*)&g_h[b * Uz + jc]);
            float hn0 = uu.x * ho.x + (1.f - uu.x) * c0;
            float hn1 = uu.y * ho.y + (1.f - uu.y) * c1;
            __stcg((float2*)&g_h[b * Uz + jc], make_float2(hn0, hn1));
            *(float2*)&y[(size_t)m * Uz + jc] = make_float2(hn0, hn1);
        }
        gsync();
    }

    {
        int i = blk * NTHR + tid;
        s_out[i] = __ldcg(&g_h[i]);
    }
}

// ------------------------------------------------------------------
extern "C" void kernel_launch(void* const* d_in, const int* in_sizes, int n_in,
                              void* d_out, int out_size)
{
    const int*   x    = (const int*)  d_in[0];
    const float* h0_0 = (const float*)d_in[1];
    const float* h0_1 = (const float*)d_in[2];
    const float* emb  = (const float*)d_in[3];
    const float* Wg0  = (const float*)d_in[4];
    const float* bg0  = (const float*)d_in[5];
    const float* Wc0  = (const float*)d_in[6];
    const float* bc0  = (const float*)d_in[7];
    const float* Wg1  = (const float*)d_in[8];
    const float* bg1  = (const float*)d_in[9];
    const float* Wc1  = (const float*)d_in[10];
    const float* bc1  = (const float*)d_in[11];
    float* out = (float*)d_out;

    float *Xg, *Xc, *y0;
    cudaGetSymbolAddress((void**)&Xg, g_Xg);
    cudaGetSymbolAddress((void**)&Xc, g_Xc);
    cudaGetSymbolAddress((void**)&y0, g_y0);

    static int smem_set = 0;
    if (!smem_set) {
        cudaFuncSetAttribute(gru_scan, cudaFuncAttributeMaxDynamicSharedMemorySize, SMEM_BYTES);
        smem_set = 1;
    }

    float* s0_out = out + (size_t)BSz * Uz;
    float* s1_out = s0_out + Bz * Uz;

    // ---------- layer 0 ----------
    sgemm_bias<<<dim3(U2 / 128, BSz / 128), 256>>>(emb, x, Wg0, bg0, Xg, BSz, U2, Ez);
    sgemm_bias<<<dim3(Uz / 128, BSz / 128), 256>>>(emb, x, Wc0, bc0, Xc, BSz, Uz, Ez);
    gru_scan<<<NBLK, NTHR, SMEM_BYTES>>>(
        Wg0 + (size_t)Ez * U2, Wc0 + (size_t)Ez * Uz, Xg, Xc, h0_0, y0, s0_out);

    // ---------- layer 1 ----------
    sgemm_bias<<<dim3(U2 / 128, BSz / 128), 256>>>(y0, nullptr, Wg1, bg1, Xg, BSz, U2, Uz);
    sgemm_bias<<<dim3(Uz / 128, BSz / 128), 256>>>(y0, nullptr, Wc1, bc1, Xc, BSz, Uz, Uz);
    gru_scan<<<NBLK, NTHR, SMEM_BYTES>>>(
        Wg1 + (size_t)Uz * U2, Wc1 + (size_t)Uz * Uz, Xg, Xc, h0_1, out, s1_out);
}

// round 4
// speedup vs baseline: 1.0948x; 1.0948x over previous
#include <cuda_runtime.h>
#include <math.h>

typedef unsigned long long ull;

#define Bz 32
#define Sz 512
#define Ez 256
#define Uz 1024
#define U2 2048
#define BSz (Bz*Sz)   // 16384

#define NBLK 128
#define NTHR 512

// -------- scratch (device globals; no allocation allowed) --------
__device__ float g_Xg[(size_t)BSz * U2];
__device__ float g_Xc[(size_t)BSz * Uz];
__device__ float g_y0[(size_t)BSz * Uz];
__device__ float g_h [Bz * Uz];
__device__ float g_u [Bz * Uz];
__device__ float g_a [Bz * Uz];

// grid barrier state
__device__ unsigned int g_count = 0;
__device__ volatile unsigned int g_gen = 0;

// -------- f32x2 packed-math helpers (pack axis = k) --------
__device__ __forceinline__ void fma2(ull& d, ull a, ull b) {
    asm("fma.rn.f32x2 %0, %1, %2, %0;" : "+l"(d) : "l"(a), "l"(b));
}
__device__ __forceinline__ void add2(ull& d, ull a) {
    asm("add.rn.f32x2 %0, %1, %0;" : "+l"(d) : "l"(a));
}
__device__ __forceinline__ float hadd2(ull v) {
    float2 r; asm("mov.b64 {%0,%1}, %2;" : "=f"(r.x), "=f"(r.y) : "l"(v));
    return r.x + r.y;
}

__device__ __forceinline__ void gsync() {
    __syncthreads();
    if (threadIdx.x == 0) {
        __threadfence();
        unsigned int gen = g_gen;
        if (atomicAdd(&g_count, 1u) == NBLK - 1u) {
            g_count = 0;
            __threadfence();
            g_gen = gen + 1u;
        } else {
            while (g_gen == gen) { }
        }
        __threadfence();
    }
    __syncthreads();
}

// ------------------------------------------------------------------
// Round-2 GEMM verbatim (scalar FFMA, 2 blocks/SM).
__global__ __launch_bounds__(256) void sgemm_bias(
    const float* __restrict__ Abase, const int* __restrict__ xidx,
    const float* __restrict__ W, const float* __restrict__ bias,
    float* __restrict__ C, int M, int N, int K)
{
    __shared__ float As[8][128];
    __shared__ float Bs[8][128];

    int tid = threadIdx.x;
    int ty = tid >> 4;
    int tx = tid & 15;
    int rowBase = blockIdx.y * 128;
    int colBase = blockIdx.x * 128;

    int arow  = tid >> 1;
    int acol4 = (tid & 1) * 4;
    int am = rowBase + arow;
    const float* arowptr;
    if (xidx) arowptr = Abase + (size_t)xidx[am] * K;
    else      arowptr = Abase + (size_t)am * K;

    int brow  = tid >> 5;
    int bcol4 = (tid & 31) * 4;

    float acc[8][8];
#pragma unroll
    for (int i = 0; i < 8; i++)
#pragma unroll
        for (int j = 0; j < 8; j++) acc[i][j] = 0.f;

    for (int k0 = 0; k0 < K; k0 += 8) {
        float4 av = *(const float4*)&arowptr[k0 + acol4];
        As[acol4 + 0][arow] = av.x;
        As[acol4 + 1][arow] = av.y;
        As[acol4 + 2][arow] = av.z;
        As[acol4 + 3][arow] = av.w;

        float4 bv = *(const float4*)&W[(size_t)(k0 + brow) * N + colBase + bcol4];
        *(float4*)&Bs[brow][bcol4] = bv;

        __syncthreads();
#pragma unroll
        for (int kk = 0; kk < 8; kk++) {
            float4 a0 = *(const float4*)&As[kk][ty * 8];
            float4 a1 = *(const float4*)&As[kk][ty * 8 + 4];
            float4 b0 = *(const float4*)&Bs[kk][tx * 8];
            float4 b1 = *(const float4*)&Bs[kk][tx * 8 + 4];
            float ar[8] = {a0.x,a0.y,a0.z,a0.w,a1.x,a1.y,a1.z,a1.w};
            float br[8] = {b0.x,b0.y,b0.z,b0.w,b1.x,b1.y,b1.z,b1.w};
#pragma unroll
            for (int i = 0; i < 8; i++)
#pragma unroll
                for (int j = 0; j < 8; j++)
                    acc[i][j] = fmaf(ar[i], br[j], acc[i][j]);
        }
        __syncthreads();
    }

    int col0 = colBase + tx * 8;
    float4 bia0 = *(const float4*)&bias[col0];
    float4 bia1 = *(const float4*)&bias[col0 + 4];
#pragma unroll
    for (int i = 0; i < 8; i++) {
        int row = rowBase + ty * 8 + i;
        float4 v0, v1;
        v0.x = acc[i][0] + bia0.x; v0.y = acc[i][1] + bia0.y;
        v0.z = acc[i][2] + bia0.z; v0.w = acc[i][3] + bia0.w;
        v1.x = acc[i][4] + bia1.x; v1.y = acc[i][5] + bia1.y;
        v1.z = acc[i][6] + bia1.z; v1.w = acc[i][7] + bia1.w;
        *(float4*)&C[(size_t)row * N + col0]     = v0;
        *(float4*)&C[(size_t)row * N + col0 + 4] = v1;
    }
}

// ------------------------------------------------------------------
// Persistent GRU scan. 128 blocks x 512 threads.
// tid -> kh = tid>>8 (k-half), r = tid&255, b = r>>3 (batch), jj = r&7.
// Phase1: thread computes gate cols jg0+2jj, jg0+2jj+1 over its 512-k half.
// Phase2: thread computes cand col jc0+jj over its 512-k half.
// W stored TRANSPOSED [col][k] in SMEM -> k-contiguous pairs for f32x2.
// h/a staged whole (32x1024 floats) once per phase.
//
// SMEM bytes: swg 8*8208 = 65664, swc 8*4112 = 32896, sh 131072  -> 229632
#define SWG_BYTES 65664
#define SWC_BYTES 32896
#define SH_BYTES  131072
#define SMEM_BYTES (SWG_BYTES + SWC_BYTES + SH_BYTES)

__global__ __launch_bounds__(NTHR) void gru_scan(
    const float* __restrict__ Wgh,   // [1024][2048]
    const float* __restrict__ Wch,   // [1024][1024]
    const float* __restrict__ Xg,    // [16384][2048]
    const float* __restrict__ Xc,    // [16384][1024]
    const float* __restrict__ h0,
    float* __restrict__ y,
    float* __restrict__ s_out)
{
    extern __shared__ char smraw[];
    char*  swg = smraw;                         // transposed gate W slice
    char*  swc = smraw + SWG_BYTES;             // transposed cand W slice
    float* sh  = (float*)(smraw + SWG_BYTES + SWC_BYTES);   // 32x1024 h/a tile
    ull*   red = (ull*)sh;                      // reduction scratch (reused)

    const int tid = threadIdx.x;
    const int blk = blockIdx.x;
    const int kh  = tid >> 8;      // 0/1
    const int r   = tid & 255;
    const int b   = r >> 3;        // 0..31
    const int jj  = r & 7;         // 0..7
    const int jg0 = blk * 16;
    const int jc0 = blk * 8;

    // ---- preload W slices, transposed (once per layer) ----
    // swg layout: col c (0..15) at byte (c>>1)*8208 + (c&1)*4096, k contiguous.
    for (int i = tid; i < 4096; i += NTHR) {
        int k = i >> 2, c4 = (i & 3) * 4;
        float4 v = *(const float4*)&Wgh[(size_t)k * U2 + jg0 + c4];
        float vv[4] = {v.x, v.y, v.z, v.w};
#pragma unroll
        for (int d = 0; d < 4; d++) {
            int c = c4 + d;
            *(float*)(swg + (c >> 1) * 8208 + (c & 1) * 4096 + k * 4) = vv[d];
        }
    }
    // swc layout: col c (0..7) at byte c*4112, k contiguous.
    for (int i = tid; i < 2048; i += NTHR) {
        int k = i >> 1, cb = (i & 1) * 4;
        float4 v = *(const float4*)&Wch[(size_t)k * Uz + jc0 + cb];
        float vv[4] = {v.x, v.y, v.z, v.w};
#pragma unroll
        for (int d = 0; d < 4; d++)
            *(float*)(swc + (cb + d) * 4112 + k * 4) = vv[d];
    }
    {
        int i = blk * NTHR + tid;
        if (i < Bz * Uz) __stcg(&g_h[i], h0[i]);
    }
    gsync();

    for (int t = 0; t < Sz; t++) {
        // ======== phase 1: stage h, compute gates ========
        {
            const float4* src = (const float4*)g_h;
            float4* dst = (float4*)sh;
#pragma unroll 4
            for (int rr = 0; rr < 16; rr++) {
                int i = tid + rr * NTHR;
                dst[i] = __ldcg(src + i);
            }
        }
        __syncthreads();

        ull acc0a = 0, acc0b = 0, acc1a = 0, acc1b = 0;
        {
            const ulonglong2* hp  = (const ulonglong2*)(sh + b * 1024 + kh * 512);
            const ulonglong2* w0p = (const ulonglong2*)(swg + jj * 8208 + kh * 2048);
            const ulonglong2* w1p = (const ulonglong2*)(swg + jj * 8208 + 4096 + kh * 2048);
#pragma unroll 2
            for (int i = 0; i < 128; i += 4) {
                ulonglong2 h0v = hp[i], h1v = hp[i+1], h2v = hp[i+2], h3v = hp[i+3];
                ulonglong2 a0 = w0p[i], a1 = w0p[i+1], a2 = w0p[i+2], a3 = w0p[i+3];
                fma2(acc0a, h0v.x, a0.x); fma2(acc0b, h0v.y, a0.y);
                fma2(acc0a, h1v.x, a1.x); fma2(acc0b, h1v.y, a1.y);
                fma2(acc0a, h2v.x, a2.x); fma2(acc0b, h2v.y, a2.y);
                fma2(acc0a, h3v.x, a3.x); fma2(acc0b, h3v.y, a3.y);
                ulonglong2 b0 = w1p[i], b1 = w1p[i+1], b2 = w1p[i+2], b3 = w1p[i+3];
                fma2(acc1a, h0v.x, b0.x); fma2(acc1b, h0v.y, b0.y);
                fma2(acc1a, h1v.x, b1.x); fma2(acc1b, h1v.y, b1.y);
                fma2(acc1a, h2v.x, b2.x); fma2(acc1b, h2v.y, b2.y);
                fma2(acc1a, h3v.x, b3.x); fma2(acc1b, h3v.y, b3.y);
            }
        }
        add2(acc0a, acc0b);
        add2(acc1a, acc1b);

        __syncthreads();
        if (kh) { red[r * 2] = acc0a; red[r * 2 + 1] = acc1a; }
        __syncthreads();
        if (!kh) {
            add2(acc0a, red[r * 2]);
            add2(acc1a, red[r * 2 + 1]);
            float s0 = hadd2(acc0a);
            float s1 = hadd2(acc1a);
            int jg = jg0 + jj * 2;
            int m  = b * Sz + t;
            float2 xg = *(const float2*)&Xg[(size_t)m * U2 + jg];
            float v0 = 1.f / (1.f + expf(-(xg.x + s0)));
            float v1 = 1.f / (1.f + expf(-(xg.y + s1)));
            if (jg < Uz) {
                float2 hv = __ldcg((const float2*)&g_h[b * Uz + jg]);
                __stcg((float2*)&g_a[b * Uz + jg], make_float2(v0 * hv.x, v1 * hv.y));
            } else {
                __stcg((float2*)&g_u[b * Uz + jg - Uz], make_float2(v0, v1));
            }
        }
        gsync();

        // ======== phase 2: stage a, compute candidate + update ========
        {
            const float4* src = (const float4*)g_a;
            float4* dst = (float4*)sh;
#pragma unroll 4
            for (int rr = 0; rr < 16; rr++) {
                int i = tid + rr * NTHR;
                dst[i] = __ldcg(src + i);
            }
        }
        __syncthreads();

        ull ca = 0, cb2 = 0;
        {
            const ulonglong2* ap = (const ulonglong2*)(sh + b * 1024 + kh * 512);
            const ulonglong2* wp = (const ulonglong2*)(swc + jj * 4112 + kh * 2048);
#pragma unroll 2
            for (int i = 0; i < 128; i += 4) {
                ulonglong2 a0 = ap[i], a1 = ap[i+1], a2 = ap[i+2], a3 = ap[i+3];
                ulonglong2 w0 = wp[i], w1 = wp[i+1], w2 = wp[i+2], w3 = wp[i+3];
                fma2(ca, a0.x, w0.x); fma2(cb2, a0.y, w0.y);
                fma2(ca, a1.x, w1.x); fma2(cb2, a1.y, w1.y);
                fma2(ca, a2.x, w2.x); fma2(cb2, a2.y, w2.y);
                fma2(ca, a3.x, w3.x); fma2(cb2, a3.y, w3.y);
            }
        }
        add2(ca, cb2);

        __syncthreads();
        if (kh) red[r] = ca;
        __syncthreads();
        if (!kh) {
            add2(ca, red[r]);
            float cs = hadd2(ca);
            int jc = jc0 + jj;
            int m  = b * Sz + t;
            float c  = tanhf(Xc[(size_t)m * Uz + jc] + cs);
            float uu = __ldcg(&g_u[b * Uz + jc]);
            float ho = __ldcg(&g_h[b * Uz + jc]);
            float hn = uu * ho + (1.f - uu) * c;
            __stcg(&g_h[b * Uz + jc], hn);
            y[(size_t)m * Uz + jc] = hn;
        }
        gsync();
    }

    {
        int i = blk * NTHR + tid;
        if (i < Bz * Uz) s_out[i] = __ldcg(&g_h[i]);
    }
}

// ------------------------------------------------------------------
extern "C" void kernel_launch(void* const* d_in, const int* in_sizes, int n_in,
                              void* d_out, int out_size)
{
    const int*   x    = (const int*)  d_in[0];
    const float* h0_0 = (const float*)d_in[1];
    const float* h0_1 = (const float*)d_in[2];
    const float* emb  = (const float*)d_in[3];
    const float* Wg0  = (const float*)d_in[4];
    const float* bg0  = (const float*)d_in[5];
    const float* Wc0  = (const float*)d_in[6];
    const float* bc0  = (const float*)d_in[7];
    const float* Wg1  = (const float*)d_in[8];
    const float* bg1  = (const float*)d_in[9];
    const float* Wc1  = (const float*)d_in[10];
    const float* bc1  = (const float*)d_in[11];
    float* out = (float*)d_out;

    float *Xg, *Xc, *y0;
    cudaGetSymbolAddress((void**)&Xg, g_Xg);
    cudaGetSymbolAddress((void**)&Xc, g_Xc);
    cudaGetSymbolAddress((void**)&y0, g_y0);

    static int smem_set = 0;
    if (!smem_set) {
        cudaFuncSetAttribute(gru_scan, cudaFuncAttributeMaxDynamicSharedMemorySize, SMEM_BYTES);
        smem_set = 1;
    }

    float* s0_out = out + (size_t)BSz * Uz;
    float* s1_out = s0_out + Bz * Uz;

    // ---------- layer 0 ----------
    sgemm_bias<<<dim3(U2 / 128, BSz / 128), 256>>>(emb, x, Wg0, bg0, Xg, BSz, U2, Ez);
    sgemm_bias<<<dim3(Uz / 128, BSz / 128), 256>>>(emb, x, Wc0, bc0, Xc, BSz, Uz, Ez);
    gru_scan<<<NBLK, NTHR, SMEM_BYTES>>>(
        Wg0 + (size_t)Ez * U2, Wc0 + (size_t)Ez * Uz, Xg, Xc, h0_0, y0, s0_out);

    // ---------- layer 1 ----------
    sgemm_bias<<<dim3(U2 / 128, BSz / 128), 256>>>(y0, nullptr, Wg1, bg1, Xg, BSz, U2, Uz);
    sgemm_bias<<<dim3(Uz / 128, BSz / 128), 256>>>(y0, nullptr, Wc1, bc1, Xc, BSz, Uz, Uz);
    gru_scan<<<NBLK, NTHR, SMEM_BYTES>>>(
        Wg1 + (size_t)Uz * U2, Wc1 + (size_t)Uz * Uz, Xg, Xc, h0_1, out, s1_out);
}